// round 9
// baseline (speedup 1.0000x reference)
#include <cuda_runtime.h>
#include <cuda_bf16.h>
#include <cstdint>

#define B_ 4
#define C_ 16
#define H_ 512
#define W_ 512
#define HW_ (H_ * W_)            // 262144
#define NPIX_ (B_ * HW_)         // 1048576
#define HALFPIX_ (NPIX_ / 2)     // 524288 (batches 0,1 | 2,3)
#define EPS_ 1e-10f

// Scratch: packed (priority<<32 | float_bits(Z)) per output pixel. 8 MB.
// Zero at module load; final_kernel re-zeros after consuming -> replay-safe.
__device__ unsigned long long g_scratch[NPIX_];

// Side stream + events for capture-legal cross-stream pipelining.
static cudaStream_t g_s1;
static cudaEvent_t  g_eA, g_eB, g_eC;
static struct HxInit {
    HxInit() {
        cudaStreamCreateWithFlags(&g_s1, cudaStreamNonBlocking);
        cudaEventCreateWithFlags(&g_eA, cudaEventDisableTiming);
        cudaEventCreateWithFlags(&g_eB, cudaEventDisableTiming);
        cudaEventCreateWithFlags(&g_eC, cudaEventDisableTiming);
    }
} g_hx_init;

// ---------------------------------------------------------------------------
// Main: unproject -> last-mask transform -> reproject -> priority scatter.
// Processes one HALF (2 batches). 2 px/thread, 512 px/block (batch-uniform).
// Hybrid mask scan: 15..12 batched, fallback 11..4, then 3..0.
// ---------------------------------------------------------------------------
__global__ void __launch_bounds__(256)
main_kernel(const float* __restrict__ depth,
            const float* __restrict__ K,
            const float* __restrict__ T,
            const void* __restrict__ masks,
            int half) {
    __shared__ float sT[C_ * 16];
    __shared__ float sK[9];
    __shared__ float sKi[9];
    __shared__ int   s_bad;

    const int tid  = threadIdx.x;
    const int base = half * HALFPIX_ + blockIdx.x * 512;
    const int b    = base >> 18;               // batch (constant per block)

    if (tid == 0) {
        s_bad = 0;
        const float* k = K + b * 9;
        float a = k[0], bb = k[1], c = k[2];
        float d = k[3], e  = k[4], f = k[5];
        float g = k[6], h  = k[7], i = k[8];
        float A  =  (e * i - f * h);
        float Bc = -(d * i - f * g);
        float Cc =  (d * h - e * g);
        float det = a * A + bb * Bc + c * Cc;
        float inv = 1.0f / det;
        sKi[0] = A * inv;
        sKi[1] = -(bb * i - c * h) * inv;
        sKi[2] =  (bb * f - c * e) * inv;
        sKi[3] = Bc * inv;
        sKi[4] =  (a * i - c * g) * inv;
        sKi[5] = -(a * f - c * d) * inv;
        sKi[6] = Cc * inv;
        sKi[7] = -(a * h - bb * g) * inv;
        sKi[8] =  (a * e - bb * d) * inv;
    }
    sT[tid] = T[b * (C_ * 16) + tid];
    if (tid < 9) sK[tid] = K[b * 9 + tid];
    __syncthreads();

    // Mask dtype sniff: 128 threads read first 512 bytes as u32.
    if (tid < 128) {
        unsigned wv = ((const unsigned*)masks)[tid];
        if (wv > 1u) atomicOr(&s_bad, 1);
    }
    __syncthreads();
    const bool mask_is_i32 = (s_bad == 0);

    const int idx = base + tid * 2;
    const int rem = idx & (HW_ - 1);
    const int v   = rem >> 9;
    const int u   = rem & (W_ - 1);

    const float2 d2 = *(const float2*)(depth + idx);
    const float  dd[2] = {d2.x, d2.y};

    // Last set channel per pixel. "Any unresolved" test is OR, not AND.
    const long mbase = (long)b * (C_ * HW_) + rem;
    int cw[2] = {-1, -1};
    if (mask_is_i32) {
        const int* m = (const int*)masks;
        {   // channels 15..12
            int2 a[4];
            #pragma unroll
            for (int j = 0; j < 4; ++j)
                a[j] = __ldg((const int2*)(m + mbase + (long)(12 + j) * HW_));
            #pragma unroll
            for (int j = 3; j >= 0; --j) {
                if (cw[0] < 0 && a[j].x) cw[0] = 12 + j;
                if (cw[1] < 0 && a[j].y) cw[1] = 12 + j;
            }
        }
        if ((cw[0] | cw[1]) < 0) {                 // channels 11..4
            int2 a[8];
            #pragma unroll
            for (int j = 0; j < 8; ++j)
                a[j] = __ldg((const int2*)(m + mbase + (long)(4 + j) * HW_));
            #pragma unroll
            for (int j = 7; j >= 0; --j) {
                if (cw[0] < 0 && a[j].x) cw[0] = 4 + j;
                if (cw[1] < 0 && a[j].y) cw[1] = 4 + j;
            }
            if ((cw[0] | cw[1]) < 0) {             // channels 3..0
                int2 a2[4];
                #pragma unroll
                for (int j = 0; j < 4; ++j)
                    a2[j] = __ldg((const int2*)(m + mbase + (long)j * HW_));
                #pragma unroll
                for (int j = 3; j >= 0; --j) {
                    if (cw[0] < 0 && a2[j].x) cw[0] = j;
                    if (cw[1] < 0 && a2[j].y) cw[1] = j;
                }
            }
        }
    } else {
        const unsigned char* mb = (const unsigned char*)masks;
        {   // channels 15..12
            unsigned short a[4];
            #pragma unroll
            for (int j = 0; j < 4; ++j)
                a[j] = *(const unsigned short*)(mb + mbase + (long)(12 + j) * HW_);
            #pragma unroll
            for (int j = 3; j >= 0; --j) {
                if (cw[0] < 0 && (a[j] & 0x00ffu)) cw[0] = 12 + j;
                if (cw[1] < 0 && (a[j] & 0xff00u)) cw[1] = 12 + j;
            }
        }
        if ((cw[0] | cw[1]) < 0) {                 // channels 11..4
            unsigned short a[8];
            #pragma unroll
            for (int j = 0; j < 8; ++j)
                a[j] = *(const unsigned short*)(mb + mbase + (long)(4 + j) * HW_);
            #pragma unroll
            for (int j = 7; j >= 0; --j) {
                if (cw[0] < 0 && (a[j] & 0x00ffu)) cw[0] = 4 + j;
                if (cw[1] < 0 && (a[j] & 0xff00u)) cw[1] = 4 + j;
            }
            if ((cw[0] | cw[1]) < 0) {             // channels 3..0
                unsigned short a2[4];
                #pragma unroll
                for (int j = 0; j < 4; ++j)
                    a2[j] = *(const unsigned short*)(mb + mbase + (long)j * HW_);
                #pragma unroll
                for (int j = 3; j >= 0; --j) {
                    if (cw[0] < 0 && (a2[j] & 0x00ffu)) cw[0] = j;
                    if (cw[1] < 0 && (a2[j] & 0xff00u)) cw[1] = j;
                }
            }
        }
    }

    const float vf = (float)v;
    #pragma unroll
    for (int p = 0; p < 2; ++p) {
        const float uf = (float)(u + p);
        const float d  = dd[p];

        float x = (sKi[0] * uf + sKi[1] * vf + sKi[2]) * d;
        float y = (sKi[3] * uf + sKi[4] * vf + sKi[5]) * d;
        float z = (sKi[6] * uf + sKi[7] * vf + sKi[8]) * d;

        const int c = cw[p];
        if (c >= 0) {
            const float* Tm = &sT[c * 16];
            float tx = Tm[0]  * x + Tm[1]  * y + Tm[2]  * z + Tm[3];
            float ty = Tm[4]  * x + Tm[5]  * y + Tm[6]  * z + Tm[7];
            float tz = Tm[8]  * x + Tm[9]  * y + Tm[10] * z + Tm[11];
            float tw = Tm[12] * x + Tm[13] * y + Tm[14] * z + Tm[15];
            float inv = 1.0f / (tw + EPS_);
            x = tx * inv;
            y = ty * inv;
            z = tz * inv;
        }

        float phx = sK[0] * x + sK[1] * y + sK[2] * z;
        float phy = sK[3] * x + sK[4] * y + sK[5] * z;
        float phz = sK[6] * x + sK[7] * y + sK[8] * z;
        float invz = 1.0f / (phz + EPS_);
        float px = phx * invz;
        float py = phy * invz;

        int ui = (int)fminf(fmaxf(px, 0.0f), (float)(W_ - 1));
        int vi = (int)fminf(fmaxf(py, 0.0f), (float)(H_ - 1));

        unsigned long long pkt =
            ((unsigned long long)(unsigned)(rem + p + 1) << 32) |
            (unsigned long long)__float_as_uint(z);
        atomicMax(&g_scratch[b * HW_ + vi * W_ + ui], pkt);
    }
}

// ---------------------------------------------------------------------------
// Final: resolve scatter else passthrough depth; re-zero scratch.
// One HALF. 4 px/thread, 1024 px/block (R2-proven shape).
// ---------------------------------------------------------------------------
__global__ void __launch_bounds__(256)
final_kernel(const float* __restrict__ depth,
             float* __restrict__ out,
             int half) {
    const int i4 = half * HALFPIX_ + (blockIdx.x * 256 + threadIdx.x) * 4;

    ulonglong2 s01 = *(ulonglong2*)&g_scratch[i4];
    ulonglong2 s23 = *(ulonglong2*)&g_scratch[i4 + 2];
    const float4 dp = *(const float4*)(depth + i4);

    float4 o;
    o.x = s01.x ? __uint_as_float((unsigned)s01.x) : dp.x;
    o.y = s01.y ? __uint_as_float((unsigned)s01.y) : dp.y;
    o.z = s23.x ? __uint_as_float((unsigned)s23.x) : dp.z;
    o.w = s23.y ? __uint_as_float((unsigned)s23.y) : dp.w;
    *(float4*)(out + i4) = o;

    const ulonglong2 zz = {0ull, 0ull};
    *(ulonglong2*)&g_scratch[i4]     = zz;
    *(ulonglong2*)&g_scratch[i4 + 2] = zz;
}

extern "C" void kernel_launch(void* const* d_in, const int* in_sizes, int n_in,
                              void* d_out, int out_size) {
    const float* depth = (const float*)d_in[0];
    const float* K     = (const float*)d_in[1];
    const float* T     = (const float*)d_in[2];
    const void*  masks = d_in[3];
    float* out = (float*)d_out;

    // Pipelined by batch halves: finalH0 runs on g_s1 concurrently with
    // mainH1 on the capture stream. Scatter never crosses batch boundaries,
    // so the halves' scratch regions are disjoint.
    main_kernel<<<HALFPIX_ / 512, 256>>>(depth, K, T, masks, 0);
    cudaEventRecord(g_eA, 0);
    main_kernel<<<HALFPIX_ / 512, 256>>>(depth, K, T, masks, 1);
    cudaEventRecord(g_eB, 0);

    cudaStreamWaitEvent(g_s1, g_eA, 0);
    final_kernel<<<HALFPIX_ / 1024, 256, 0, g_s1>>>(depth, out, 0);
    cudaStreamWaitEvent(g_s1, g_eB, 0);
    final_kernel<<<HALFPIX_ / 1024, 256, 0, g_s1>>>(depth, out, 1);
    cudaEventRecord(g_eC, g_s1);

    cudaStreamWaitEvent(0, g_eC, 0);
}

// round 10
// speedup vs baseline: 1.2145x; 1.2145x over previous
#include <cuda_runtime.h>
#include <cuda_bf16.h>
#include <cstdint>

#define B_ 4
#define C_ 16
#define H_ 512
#define W_ 512
#define HW_ (H_ * W_)            // 262144
#define NPIX_ (B_ * HW_)         // 1048576
#define EPS_ 1e-10f

// Scratch: packed (priority<<32 | float_bits(Z)) per output pixel. 8 MB.
// Zero at module load; final_kernel re-zeros after consuming -> replay-safe.
__device__ unsigned long long g_scratch[NPIX_];

// ---------------------------------------------------------------------------
// Main: unproject -> last-mask transform -> reproject -> priority scatter.
// 4 px/thread. T staged in shared as float4 rows -> LDS.128 fetches.
// Hybrid mask scan: 15..12 batched, fallback 11..4, then 3..0.
// ---------------------------------------------------------------------------
__global__ void __launch_bounds__(256)
main_kernel(const float* __restrict__ depth,
            const float* __restrict__ K,
            const float* __restrict__ T,
            const void* __restrict__ masks) {
    __shared__ float4 sT4[C_ * 4];   // T rows as float4: sT4[c*4 + r]
    __shared__ float  sK[9];
    __shared__ float  sKi[9];
    __shared__ int    s_bad;

    const int tid  = threadIdx.x;
    const int base = blockIdx.x * 1024;
    const int b    = base >> 18;               // batch (constant per block)

    if (tid == 0) {
        s_bad = 0;
        const float* k = K + b * 9;
        float a = k[0], bb = k[1], c = k[2];
        float d = k[3], e  = k[4], f = k[5];
        float g = k[6], h  = k[7], i = k[8];
        float A  =  (e * i - f * h);
        float Bc = -(d * i - f * g);
        float Cc =  (d * h - e * g);
        float det = a * A + bb * Bc + c * Cc;
        float inv = 1.0f / det;
        sKi[0] = A * inv;
        sKi[1] = -(bb * i - c * h) * inv;
        sKi[2] =  (bb * f - c * e) * inv;
        sKi[3] = Bc * inv;
        sKi[4] =  (a * i - c * g) * inv;
        sKi[5] = -(a * f - c * d) * inv;
        sKi[6] = Cc * inv;
        sKi[7] = -(a * h - bb * g) * inv;
        sKi[8] =  (a * e - bb * d) * inv;
    }
    if (tid < 64) sT4[tid] = ((const float4*)(T + b * (C_ * 16)))[tid];
    if (tid < 9)  sK[tid]  = K[b * 9 + tid];
    __syncthreads();

    // Mask dtype sniff: 128 threads read first 512 bytes as u32.
    if (tid < 128) {
        unsigned wv = ((const unsigned*)masks)[tid];
        if (wv > 1u) atomicOr(&s_bad, 1);
    }
    __syncthreads();
    const bool mask_is_i32 = (s_bad == 0);

    const int idx = base + tid * 4;
    const int rem = idx & (HW_ - 1);
    const int v   = rem >> 9;
    const int u   = rem & (W_ - 1);

    const float4 d4 = *(const float4*)(depth + idx);
    const float  dd[4] = {d4.x, d4.y, d4.z, d4.w};

    // Last set channel per pixel. "Any unresolved" test is OR, not AND.
    const long mbase = (long)b * (C_ * HW_) + rem;
    int cw[4] = {-1, -1, -1, -1};
    if (mask_is_i32) {
        const int* m = (const int*)masks;
        {   // channels 15..12
            int4 a[4];
            #pragma unroll
            for (int j = 0; j < 4; ++j)
                a[j] = __ldg((const int4*)(m + mbase + (long)(12 + j) * HW_));
            #pragma unroll
            for (int j = 3; j >= 0; --j) {
                const int c = 12 + j;
                if (cw[0] < 0 && a[j].x) cw[0] = c;
                if (cw[1] < 0 && a[j].y) cw[1] = c;
                if (cw[2] < 0 && a[j].z) cw[2] = c;
                if (cw[3] < 0 && a[j].w) cw[3] = c;
            }
        }
        if ((cw[0] | cw[1] | cw[2] | cw[3]) < 0) {   // channels 11..4
            int4 a[8];
            #pragma unroll
            for (int j = 0; j < 8; ++j)
                a[j] = __ldg((const int4*)(m + mbase + (long)(4 + j) * HW_));
            #pragma unroll
            for (int j = 7; j >= 0; --j) {
                const int c = 4 + j;
                if (cw[0] < 0 && a[j].x) cw[0] = c;
                if (cw[1] < 0 && a[j].y) cw[1] = c;
                if (cw[2] < 0 && a[j].z) cw[2] = c;
                if (cw[3] < 0 && a[j].w) cw[3] = c;
            }
            if ((cw[0] | cw[1] | cw[2] | cw[3]) < 0) {   // channels 3..0
                int4 a2[4];
                #pragma unroll
                for (int j = 0; j < 4; ++j)
                    a2[j] = __ldg((const int4*)(m + mbase + (long)j * HW_));
                #pragma unroll
                for (int j = 3; j >= 0; --j) {
                    if (cw[0] < 0 && a2[j].x) cw[0] = j;
                    if (cw[1] < 0 && a2[j].y) cw[1] = j;
                    if (cw[2] < 0 && a2[j].z) cw[2] = j;
                    if (cw[3] < 0 && a2[j].w) cw[3] = j;
                }
            }
        }
    } else {
        const unsigned char* mb = (const unsigned char*)masks;
        {   // channels 15..12
            unsigned a[4];
            #pragma unroll
            for (int j = 0; j < 4; ++j)
                a[j] = __ldg((const unsigned*)(mb + mbase + (long)(12 + j) * HW_));
            #pragma unroll
            for (int j = 3; j >= 0; --j) {
                #pragma unroll
                for (int p = 0; p < 4; ++p)
                    if (cw[p] < 0 && (a[j] & (0xffu << (8 * p)))) cw[p] = 12 + j;
            }
        }
        if ((cw[0] | cw[1] | cw[2] | cw[3]) < 0) {   // channels 11..4
            unsigned a[8];
            #pragma unroll
            for (int j = 0; j < 8; ++j)
                a[j] = __ldg((const unsigned*)(mb + mbase + (long)(4 + j) * HW_));
            #pragma unroll
            for (int j = 7; j >= 0; --j) {
                #pragma unroll
                for (int p = 0; p < 4; ++p)
                    if (cw[p] < 0 && (a[j] & (0xffu << (8 * p)))) cw[p] = 4 + j;
            }
            if ((cw[0] | cw[1] | cw[2] | cw[3]) < 0) {   // channels 3..0
                unsigned a2[4];
                #pragma unroll
                for (int j = 0; j < 4; ++j)
                    a2[j] = __ldg((const unsigned*)(mb + mbase + (long)j * HW_));
                #pragma unroll
                for (int j = 3; j >= 0; --j) {
                    #pragma unroll
                    for (int p = 0; p < 4; ++p)
                        if (cw[p] < 0 && (a2[j] & (0xffu << (8 * p)))) cw[p] = j;
                }
            }
        }
    }

    const float vf = (float)v;
    #pragma unroll
    for (int p = 0; p < 4; ++p) {
        const float uf = (float)(u + p);
        const float d  = dd[p];

        float x = (sKi[0] * uf + sKi[1] * vf + sKi[2]) * d;
        float y = (sKi[3] * uf + sKi[4] * vf + sKi[5]) * d;
        float z = (sKi[6] * uf + sKi[7] * vf + sKi[8]) * d;

        const int c = cw[p];
        if (c >= 0) {
            // 4x LDS.128 instead of 16x LDS.32
            const float4 r0 = sT4[c * 4 + 0];
            const float4 r1 = sT4[c * 4 + 1];
            const float4 r2 = sT4[c * 4 + 2];
            const float4 r3 = sT4[c * 4 + 3];
            float tx = r0.x * x + r0.y * y + r0.z * z + r0.w;
            float ty = r1.x * x + r1.y * y + r1.z * z + r1.w;
            float tz = r2.x * x + r2.y * y + r2.z * z + r2.w;
            float tw = r3.x * x + r3.y * y + r3.z * z + r3.w;
            float inv = 1.0f / (tw + EPS_);
            x = tx * inv;
            y = ty * inv;
            z = tz * inv;
        }

        float phx = sK[0] * x + sK[1] * y + sK[2] * z;
        float phy = sK[3] * x + sK[4] * y + sK[5] * z;
        float phz = sK[6] * x + sK[7] * y + sK[8] * z;
        float invz = 1.0f / (phz + EPS_);
        float px = phx * invz;
        float py = phy * invz;

        int ui = (int)fminf(fmaxf(px, 0.0f), (float)(W_ - 1));
        int vi = (int)fminf(fmaxf(py, 0.0f), (float)(H_ - 1));

        unsigned long long pkt =
            ((unsigned long long)(unsigned)(rem + p + 1) << 32) |
            (unsigned long long)__float_as_uint(z);
        atomicMax(&g_scratch[b * HW_ + vi * W_ + ui], pkt);
    }
}

// ---------------------------------------------------------------------------
// Final: resolve scatter else passthrough depth; re-zero scratch.
// 2 px/thread, 2048 blocks -> max warp-level latency hiding.
// ---------------------------------------------------------------------------
__global__ void __launch_bounds__(256)
final_kernel(const float* __restrict__ depth,
             float* __restrict__ out) {
    const int i2 = (blockIdx.x * 256 + threadIdx.x) * 2;

    ulonglong2 s = *(ulonglong2*)&g_scratch[i2];
    const float2 dp = *(const float2*)(depth + i2);

    float2 o;
    o.x = s.x ? __uint_as_float((unsigned)s.x) : dp.x;
    o.y = s.y ? __uint_as_float((unsigned)s.y) : dp.y;
    *(float2*)(out + i2) = o;

    const ulonglong2 zz = {0ull, 0ull};
    *(ulonglong2*)&g_scratch[i2] = zz;
}

extern "C" void kernel_launch(void* const* d_in, const int* in_sizes, int n_in,
                              void* d_out, int out_size) {
    const float* depth = (const float*)d_in[0];
    const float* K     = (const float*)d_in[1];
    const float* T     = (const float*)d_in[2];
    const void*  masks = d_in[3];
    float* out = (float*)d_out;

    main_kernel<<<NPIX_ / 1024, 256>>>(depth, K, T, masks);
    final_kernel<<<NPIX_ / 512, 256>>>(depth, out);
}